// round 5
// baseline (speedup 1.0000x reference)
#include <cuda_runtime.h>
#include <cstddef>

// LocalVariation: out[b,k,y,x] = x[b,y,x] - x[b, clamp(y+i-2), clamp(x+j-2)]
// k enumerates 24 off-center (i,j) in a 5x5 window. x: [16,1,512,512] f32.
//
// R4 (re-run after infra failure): force 32 regs/thread
// (__launch_bounds__(512,4)) for full-occupancy target -> more outstanding
// stores to saturate the HBM write stream. Live set kept minimal: centers
// (4), output base, and a per-row 8-wide window that dies before next row.

#define KSZ 5
#define P   2
#define NBR 24
#define H   512
#define W   512
#define BATCH 16
#define ROWS_PER_CTA 4
#define SROWS (ROWS_PER_CTA + KSZ - 1)   // 8 staged rows

// padded shared row: 516 valid cols (x in [-2,513]) -> stride 520 floats
#define SROW 520
#define SCOLS 516

__global__ __launch_bounds__(512, 4)
void LocalVariation_kernel(const float* __restrict__ x, float* __restrict__ out)
{
    __shared__ float s[SROWS * SROW];

    const int y0  = blockIdx.x * ROWS_PER_CTA;   // first output row of this CTA
    const int b   = blockIdx.y;                  // 0..15
    const int tid = threadIdx.x;                 // 0..511

    const float* __restrict__ xb = x + (size_t)b * H * W;

    // Stage rows y0-2 .. y0+5 (clamped) with x replicate-pad into SMEM.
    #pragma unroll 2
    for (int idx = tid; idx < SROWS * SCOLS; idx += 512) {
        const int r   = idx / SCOLS;
        const int col = idx - r * SCOLS;         // 0..515  (maps to x = col-2)
        int gy = y0 + r - P;
        gy = gy < 0 ? 0 : (gy > H - 1 ? H - 1 : gy);
        int gx = col - P;
        gx = gx < 0 ? 0 : (gx > W - 1 ? W - 1 : gx);
        s[r * SROW + col] = __ldg(&xb[gy * W + gx]);
    }
    __syncthreads();

    const int r0 = tid >> 7;           // which of the 4 output rows (0..3)
    const int x0 = (tid & 127) * 4;    // this thread's 4 output pixels

    // Incremental smem pointer; centers read once from staged row r0+2.
    const float* sp = &s[r0 * SROW + x0];
    const float c0 = sp[2 * SROW + 2];
    const float c1 = sp[2 * SROW + 3];
    const float c2 = sp[2 * SROW + 4];
    const float c3 = sp[2 * SROW + 5];

    float* __restrict__ ob =
        out + (((size_t)b * NBR) * H + (y0 + r0)) * W + x0;

    // Per input row: two aligned LDS.128 -> 8-wide window, emit that row's
    // 4-5 channel stores with compile-time plane offsets (fold into STG imm),
    // window regs die before next row.
    int k = 0;
    #pragma unroll
    for (int i = 0; i < KSZ; i++) {
        const float4 lo = *reinterpret_cast<const float4*>(sp);
        const float4 hi = *reinterpret_cast<const float4*>(sp + 4);
        const float w0 = lo.x, w1 = lo.y, w2 = lo.z, w3 = lo.w;
        const float w4 = hi.x, w5 = hi.y, w6 = hi.z, w7 = hi.w;
        sp += SROW;

        #pragma unroll
        for (int j = 0; j < KSZ; j++) {
            if (i == P && j == P) continue;
            const float n0 = (j == 0) ? w0 : (j == 1) ? w1 : (j == 2) ? w2 : (j == 3) ? w3 : w4;
            const float n1 = (j == 0) ? w1 : (j == 1) ? w2 : (j == 2) ? w3 : (j == 3) ? w4 : w5;
            const float n2 = (j == 0) ? w2 : (j == 1) ? w3 : (j == 2) ? w4 : (j == 3) ? w5 : w6;
            const float n3 = (j == 0) ? w3 : (j == 1) ? w4 : (j == 2) ? w5 : (j == 3) ? w6 : w7;
            float4 v;
            v.x = c0 - n0;
            v.y = c1 - n1;
            v.z = c2 - n2;
            v.w = c3 - n3;
            __stcs(reinterpret_cast<float4*>(ob + (size_t)k * (H * W)), v);
            k++;
        }
    }
}

extern "C" void kernel_launch(void* const* d_in, const int* in_sizes, int n_in,
                              void* d_out, int out_size)
{
    (void)in_sizes; (void)n_in; (void)out_size;
    const float* x = (const float*)d_in[0];
    float* out = (float*)d_out;
    dim3 grid(H / ROWS_PER_CTA, BATCH);
    LocalVariation_kernel<<<grid, 512>>>(x, out);
}